// round 14
// baseline (speedup 1.0000x reference)
#include <cuda_runtime.h>

// Problem constants
#define BATCH   64
#define TSTEPS  512
#define IN_DIM  1024
#define HID     1024
#define MTOT    (BATCH * TSTEPS)           // 32768 rows of the GEMM

// ALPHA = exp(-1/20) rounded to fp32
#define ALPHA_F 0.95122942450071400909f

// Scratch for the synaptic currents I[b,t,h] (128 MiB).
__device__ float g_I[(size_t)MTOT * HID];

// ---------------------------------------------------------------------------
// GEMM: g_I[m, n] = sum_k x[m, k] * W[n, k]  + b[n]
// Strictly in-order ascending-k accumulation, single fp32 accumulator, scalar
// FMA (bit-exact vs reference).
// 128x128 tile, BK=16, 256 threads.
// ROUND 11: 8x8 microtile, warp tile 32x64 (lane = 4 row-groups x 8 col-
// chunks). Per kk: 2 broadcast a-LDS.128 + 2 b-LDS.128 -> 68 issue slots per
// 64 FMA (was 69). All LDS/STS conflict-free under XOR swizzle
// col ^ ((k>>2&3)*8). Double-buffered smem + register prefetch, 1 sync/iter,
// 2 CTAs/SM.
// ---------------------------------------------------------------------------
#define BM 128
#define BN 128
#define BK 16

__global__ __launch_bounds__(256, 2)
void snn_gemm_kernel(const float* __restrict__ A,      // x  [MTOT, IN_DIM]
                     const float* __restrict__ Wt,     // W  [HID, IN_DIM]
                     const float* __restrict__ bias)   // b  [HID]
{
    __shared__ float As[2][BK][BM];   // element (k,m) at As[buf][k][m ^ swz(k)]
    __shared__ float Bs[2][BK][BN];   // element (k,n) at Bs[buf][k][n ^ swz(k)]
    // swz(k) = ((k>>2)&3)*8

    const int tid  = threadIdx.x;          // 0..255
    const int lane = tid & 31;
    const int w    = tid >> 5;             // warp 0..7
    const int row0 = blockIdx.y * BM;
    const int col0 = blockIdx.x * BN;

    // Warp tile: 32 rows x 64 cols. Lane: row-group (lane>>3)*8, col-chunk
    // (lane&7)*8.
    const int wr = (w & 3) * 32;           // warp row base within tile
    const int wc = (w >> 2) * 64;          // warp col base within tile
    const int lr = wr + (lane >> 3) * 8;   // thread row base (8 rows)
    const int lc = wc + (lane & 7) * 8;    // thread col base (8 cols)

    // Cooperative-load geometry: thread owns float4 slots f=tid, tid+256.
    const int ra = tid >> 2;               // row for slot 0 (0..63)
    const int rb = ra + 64;                // row for slot 1 (64..127)
    const int ck = (tid & 3) * 4;          // k offset within tile
    const int swz_st = (tid & 3) * 8;      // store swizzle = ((ck>>2)&3)*8
    const int ca = ra ^ swz_st;            // swizzled store col, slot 0
    const int cb = rb ^ swz_st;            // swizzled store col, slot 1

    const float* pa0 = A  + (size_t)(row0 + ra) * IN_DIM + ck;
    const float* pa1 = A  + (size_t)(row0 + rb) * IN_DIM + ck;
    const float* pw0 = Wt + (size_t)(col0 + ra) * IN_DIM + ck;
    const float* pw1 = Wt + (size_t)(col0 + rb) * IN_DIM + ck;

    float acc[8][8];
#pragma unroll
    for (int i = 0; i < 8; i++)
#pragma unroll
        for (int j = 0; j < 8; j++) acc[i][j] = 0.0f;

    // Prologue: load tile 0 into buffer 0 (swizzled scatter, conflict-free).
    {
        float4 av0 = *reinterpret_cast<const float4*>(pa0);
        float4 av1 = *reinterpret_cast<const float4*>(pa1);
        float4 wv0 = *reinterpret_cast<const float4*>(pw0);
        float4 wv1 = *reinterpret_cast<const float4*>(pw1);
        As[0][ck + 0][ca] = av0.x; As[0][ck + 1][ca] = av0.y;
        As[0][ck + 2][ca] = av0.z; As[0][ck + 3][ca] = av0.w;
        As[0][ck + 0][cb] = av1.x; As[0][ck + 1][cb] = av1.y;
        As[0][ck + 2][cb] = av1.z; As[0][ck + 3][cb] = av1.w;
        Bs[0][ck + 0][ca] = wv0.x; Bs[0][ck + 1][ca] = wv0.y;
        Bs[0][ck + 2][ca] = wv0.z; Bs[0][ck + 3][ca] = wv0.w;
        Bs[0][ck + 0][cb] = wv1.x; Bs[0][ck + 1][cb] = wv1.y;
        Bs[0][ck + 2][cb] = wv1.z; Bs[0][ck + 3][cb] = wv1.w;
    }
    __syncthreads();

    int cur = 0;
    for (int k0 = 0; k0 < IN_DIM; k0 += BK) {
        const bool has_next = (k0 + BK) < IN_DIM;

        // Prefetch next tile into registers.
        float4 av0, av1, wv0, wv1;
        if (has_next) {
            const int ko = k0 + BK;
            av0 = *reinterpret_cast<const float4*>(pa0 + ko);
            av1 = *reinterpret_cast<const float4*>(pa1 + ko);
            wv0 = *reinterpret_cast<const float4*>(pw0 + ko);
            wv1 = *reinterpret_cast<const float4*>(pw1 + ko);
        }

#pragma unroll
        for (int kk = 0; kk < BK; kk++) {
            const int swzk = ((kk >> 2) & 3) * 8;   // compile-time in unroll

            float a[8], b[8];
            *reinterpret_cast<float4*>(&a[0]) =
                *reinterpret_cast<const float4*>(&As[cur][kk][(lr + 0) ^ swzk]);
            *reinterpret_cast<float4*>(&a[4]) =
                *reinterpret_cast<const float4*>(&As[cur][kk][(lr + 4) ^ swzk]);
            *reinterpret_cast<float4*>(&b[0]) =
                *reinterpret_cast<const float4*>(&Bs[cur][kk][(lc + 0) ^ swzk]);
            *reinterpret_cast<float4*>(&b[4]) =
                *reinterpret_cast<const float4*>(&Bs[cur][kk][(lc + 4) ^ swzk]);

#pragma unroll
            for (int i = 0; i < 8; i++)
#pragma unroll
                for (int j = 0; j < 8; j++)
                    acc[i][j] = fmaf(a[i], b[j], acc[i][j]);
        }

        if (has_next) {
            const int nxt = cur ^ 1;
            As[nxt][ck + 0][ca] = av0.x; As[nxt][ck + 1][ca] = av0.y;
            As[nxt][ck + 2][ca] = av0.z; As[nxt][ck + 3][ca] = av0.w;
            As[nxt][ck + 0][cb] = av1.x; As[nxt][ck + 1][cb] = av1.y;
            As[nxt][ck + 2][cb] = av1.z; As[nxt][ck + 3][cb] = av1.w;
            Bs[nxt][ck + 0][ca] = wv0.x; Bs[nxt][ck + 1][ca] = wv0.y;
            Bs[nxt][ck + 2][ca] = wv0.z; Bs[nxt][ck + 3][ca] = wv0.w;
            Bs[nxt][ck + 0][cb] = wv1.x; Bs[nxt][ck + 1][cb] = wv1.y;
            Bs[nxt][ck + 2][cb] = wv1.z; Bs[nxt][ck + 3][cb] = wv1.w;
        }
        __syncthreads();
        cur ^= 1;
    }

    // Bias: single rounded add after the full K sum (matches "einsum + b").
    const int c = col0 + lc;
    const float4 bv0 = *reinterpret_cast<const float4*>(&bias[c]);
    const float4 bv1 = *reinterpret_cast<const float4*>(&bias[c + 4]);
#pragma unroll
    for (int i = 0; i < 8; i++) {
        const int r = row0 + lr + i;
        float4 o0, o1;
        o0.x = __fadd_rn(acc[i][0], bv0.x);
        o0.y = __fadd_rn(acc[i][1], bv0.y);
        o0.z = __fadd_rn(acc[i][2], bv0.z);
        o0.w = __fadd_rn(acc[i][3], bv0.w);
        o1.x = __fadd_rn(acc[i][4], bv1.x);
        o1.y = __fadd_rn(acc[i][5], bv1.y);
        o1.z = __fadd_rn(acc[i][6], bv1.z);
        o1.w = __fadd_rn(acc[i][7], bv1.w);
        *reinterpret_cast<float4*>(&g_I[(size_t)r * HID + c])     = o0;
        *reinterpret_cast<float4*>(&g_I[(size_t)r * HID + c + 4]) = o1;
    }
}

// ---------------------------------------------------------------------------
// LIF scan: one thread per (b, h) neuron, sequential over t.
// mem = fma.rn(alpha, mem, I); spike = (mem >= 1); hard reset.
// ROUND 11: flat unroll 32 (MLP=32, 8MB in flight chip-wide).
// ---------------------------------------------------------------------------
__global__ __launch_bounds__(128)
void snn_scan_kernel(float* __restrict__ spikes,     // [B, T, H]
                     float* __restrict__ mem_final)  // [B, H]
{
    const int idx = blockIdx.x * blockDim.x + threadIdx.x;   // 0..65535
    const int b = idx >> 10;          // / HID
    const int h = idx & (HID - 1);

    const float* ip = g_I + (size_t)b * TSTEPS * HID + h;
    float* sp = spikes + (size_t)b * TSTEPS * HID + h;

    float mem = 0.0f;
    for (int t0 = 0; t0 < TSTEPS; t0 += 32) {
        float cur[32];
#pragma unroll
        for (int u = 0; u < 32; u++)
            cur[u] = __ldcg(ip + (size_t)(t0 + u) * HID);

        float sv[32];
#pragma unroll
        for (int u = 0; u < 32; u++) {
            mem = fmaf(ALPHA_F, mem, cur[u]);    // fused: one rounding
            const bool fire = (mem >= 1.0f);
            sv[u] = fire ? 1.0f : 0.0f;
            if (fire) mem = 0.0f;
        }
#pragma unroll
        for (int u = 0; u < 32; u++)
            __stcg(sp + (size_t)(t0 + u) * HID, sv[u]);
    }
    mem_final[idx] = mem;
}

// ---------------------------------------------------------------------------
// Launch
// ---------------------------------------------------------------------------
extern "C" void kernel_launch(void* const* d_in, const int* in_sizes, int n_in,
                              void* d_out, int out_size)
{
    const float* x = (const float*)d_in[0];   // [B, T, IN_DIM]
    const float* W = (const float*)d_in[1];   // [HID, IN_DIM]
    const float* b = (const float*)d_in[2];   // [HID]

    float* out        = (float*)d_out;
    float* spikes     = out;                                  // [B, T, H]
    float* mem_final  = out + (size_t)BATCH * TSTEPS * HID;   // [B, H]

    dim3 ggrid(HID / BN, MTOT / BM);    // (8, 256)
    snn_gemm_kernel<<<ggrid, 256>>>(x, W, b);

    snn_scan_kernel<<<(BATCH * HID) / 128, 128>>>(spikes, mem_final);
}

// round 16
// speedup vs baseline: 1.1419x; 1.1419x over previous
#include <cuda_runtime.h>

// Problem constants
#define BATCH   64
#define TSTEPS  512
#define IN_DIM  1024
#define HID     1024
#define MTOT    (BATCH * TSTEPS)           // 32768 rows of the GEMM

// ALPHA = exp(-1/20) rounded to fp32
#define ALPHA_F 0.95122942450071400909f

// Scratch for the synaptic currents I[b,t,h] (128 MiB).
__device__ float g_I[(size_t)MTOT * HID];

// ---------------------------------------------------------------------------
// GEMM: g_I[m, n] = sum_k x[m, k] * W[n, k]  + b[n]
// Strictly in-order ascending-k accumulation, single fp32 accumulator, scalar
// FMA (bit-exact vs reference).
// 128x128 tile, BK=16, 256 threads, 16x4 microtile (warp=16 rows, lane=4 cols)
// XOR-swizzled smem (col ^ ((k>>2&3)*8)) -> conflict-free STS and LDS;
// b-fragment is one contiguous LDS.128 per kk; a-fragment is broadcast.
// Double-buffered smem + register prefetch, 1 sync/iter, 2 CTAs/SM.
// (Exact Round-9 configuration — validated 1281.8us total.)
// ---------------------------------------------------------------------------
#define BM 128
#define BN 128
#define BK 16

__global__ __launch_bounds__(256, 2)
void snn_gemm_kernel(const float* __restrict__ A,      // x  [MTOT, IN_DIM]
                     const float* __restrict__ Wt,     // W  [HID, IN_DIM]
                     const float* __restrict__ bias)   // b  [HID]
{
    __shared__ float As[2][BK][BM];   // element (k,m) at As[buf][k][m ^ swz(k)]
    __shared__ float Bs[2][BK][BN];   // element (k,n) at Bs[buf][k][n ^ swz(k)]
    // swz(k) = ((k>>2)&3)*8

    const int tid  = threadIdx.x;          // 0..255
    const int lane = tid & 31;             // 4 cols each: cols lane*4..+3
    const int w    = tid >> 5;             // warp: 16 rows each
    const int row0 = blockIdx.y * BM;
    const int col0 = blockIdx.x * BN;

    // Cooperative-load geometry: thread owns float4 slots f=tid, tid+256.
    const int ra = tid >> 2;               // row for slot 0 (0..63)
    const int rb = ra + 64;                // row for slot 1 (64..127)
    const int ck = (tid & 3) * 4;          // k offset within tile
    const int swz_st = (tid & 3) * 8;      // store swizzle = ((ck>>2)&3)*8
    const int ca = ra ^ swz_st;            // swizzled store col, slot 0
    const int cb = rb ^ swz_st;            // swizzled store col, slot 1

    const float* pa0 = A  + (size_t)(row0 + ra) * IN_DIM + ck;
    const float* pa1 = A  + (size_t)(row0 + rb) * IN_DIM + ck;
    const float* pw0 = Wt + (size_t)(col0 + ra) * IN_DIM + ck;
    const float* pw1 = Wt + (size_t)(col0 + rb) * IN_DIM + ck;

    float acc[16][4];
#pragma unroll
    for (int i = 0; i < 16; i++)
#pragma unroll
        for (int j = 0; j < 4; j++) acc[i][j] = 0.0f;

    // Prologue: load tile 0 into buffer 0 (swizzled scatter, conflict-free).
    {
        float4 av0 = *reinterpret_cast<const float4*>(pa0);
        float4 av1 = *reinterpret_cast<const float4*>(pa1);
        float4 wv0 = *reinterpret_cast<const float4*>(pw0);
        float4 wv1 = *reinterpret_cast<const float4*>(pw1);
        As[0][ck + 0][ca] = av0.x; As[0][ck + 1][ca] = av0.y;
        As[0][ck + 2][ca] = av0.z; As[0][ck + 3][ca] = av0.w;
        As[0][ck + 0][cb] = av1.x; As[0][ck + 1][cb] = av1.y;
        As[0][ck + 2][cb] = av1.z; As[0][ck + 3][cb] = av1.w;
        Bs[0][ck + 0][ca] = wv0.x; Bs[0][ck + 1][ca] = wv0.y;
        Bs[0][ck + 2][ca] = wv0.z; Bs[0][ck + 3][ca] = wv0.w;
        Bs[0][ck + 0][cb] = wv1.x; Bs[0][ck + 1][cb] = wv1.y;
        Bs[0][ck + 2][cb] = wv1.z; Bs[0][ck + 3][cb] = wv1.w;
    }
    __syncthreads();

    int cur = 0;
    for (int k0 = 0; k0 < IN_DIM; k0 += BK) {
        const bool has_next = (k0 + BK) < IN_DIM;

        // Prefetch next tile into registers.
        float4 av0, av1, wv0, wv1;
        if (has_next) {
            const int ko = k0 + BK;
            av0 = *reinterpret_cast<const float4*>(pa0 + ko);
            av1 = *reinterpret_cast<const float4*>(pa1 + ko);
            wv0 = *reinterpret_cast<const float4*>(pw0 + ko);
            wv1 = *reinterpret_cast<const float4*>(pw1 + ko);
        }

#pragma unroll
        for (int kk = 0; kk < BK; kk++) {
            const int swzk = ((kk >> 2) & 3) * 8;   // compile-time in unroll

            // b: one contiguous (permuted) LDS.128 — conflict-free
            float b[4];
            *reinterpret_cast<float4*>(b) =
                *reinterpret_cast<const float4*>(&Bs[cur][kk][(lane * 4) ^ swzk]);

            // a: 4 broadcast LDS.128 (all lanes same address)
            float a[16];
#pragma unroll
            for (int q = 0; q < 4; q++)
                *reinterpret_cast<float4*>(&a[q * 4]) =
                    *reinterpret_cast<const float4*>(&As[cur][kk][(w * 16 + q * 4) ^ swzk]);

#pragma unroll
            for (int i = 0; i < 16; i++)
#pragma unroll
                for (int j = 0; j < 4; j++)
                    acc[i][j] = fmaf(a[i], b[j], acc[i][j]);
        }

        if (has_next) {
            const int nxt = cur ^ 1;
            As[nxt][ck + 0][ca] = av0.x; As[nxt][ck + 1][ca] = av0.y;
            As[nxt][ck + 2][ca] = av0.z; As[nxt][ck + 3][ca] = av0.w;
            As[nxt][ck + 0][cb] = av1.x; As[nxt][ck + 1][cb] = av1.y;
            As[nxt][ck + 2][cb] = av1.z; As[nxt][ck + 3][cb] = av1.w;
            Bs[nxt][ck + 0][ca] = wv0.x; Bs[nxt][ck + 1][ca] = wv0.y;
            Bs[nxt][ck + 2][ca] = wv0.z; Bs[nxt][ck + 3][ca] = wv0.w;
            Bs[nxt][ck + 0][cb] = wv1.x; Bs[nxt][ck + 1][cb] = wv1.y;
            Bs[nxt][ck + 2][cb] = wv1.z; Bs[nxt][ck + 3][cb] = wv1.w;
        }
        __syncthreads();
        cur ^= 1;
    }

    // Bias: single rounded add after the full K sum (matches "einsum + b").
    // Per warp, each row's 32 lanes store contiguous 512B — coalesced.
    const int c = col0 + lane * 4;
    const float4 bv = *reinterpret_cast<const float4*>(&bias[c]);
#pragma unroll
    for (int i = 0; i < 16; i++) {
        const int r = row0 + w * 16 + i;
        float4 o;
        o.x = __fadd_rn(acc[i][0], bv.x);
        o.y = __fadd_rn(acc[i][1], bv.y);
        o.z = __fadd_rn(acc[i][2], bv.z);
        o.w = __fadd_rn(acc[i][3], bv.w);
        *reinterpret_cast<float4*>(&g_I[(size_t)r * HID + c]) = o;
    }
}

// ---------------------------------------------------------------------------
// LIF scan: one thread per (b, h) neuron, sequential over t.
// mem = fma.rn(alpha, mem, I); spike = (mem >= 1); hard reset.
// Unroll 16 for MLP=16 (R9 scan), ROUND 15: 64-thread blocks -> 1024 blocks
// = 6.92/SM (ceil 7, ~1% imbalance) vs 512 blocks = 3.46/SM (ceil 4, ~15%).
// ---------------------------------------------------------------------------
__global__ __launch_bounds__(64)
void snn_scan_kernel(float* __restrict__ spikes,     // [B, T, H]
                     float* __restrict__ mem_final)  // [B, H]
{
    const int idx = blockIdx.x * blockDim.x + threadIdx.x;   // 0..65535
    const int b = idx >> 10;          // / HID
    const int h = idx & (HID - 1);

    const float* ip = g_I + (size_t)b * TSTEPS * HID + h;
    float* sp = spikes + (size_t)b * TSTEPS * HID + h;

    float mem = 0.0f;
    for (int t0 = 0; t0 < TSTEPS; t0 += 16) {
        float cur[16];
#pragma unroll
        for (int u = 0; u < 16; u++)
            cur[u] = __ldcg(ip + (size_t)(t0 + u) * HID);

        float sv[16];
#pragma unroll
        for (int u = 0; u < 16; u++) {
            mem = fmaf(ALPHA_F, mem, cur[u]);    // fused: one rounding
            const bool fire = (mem >= 1.0f);
            sv[u] = fire ? 1.0f : 0.0f;
            if (fire) mem = 0.0f;
        }
#pragma unroll
        for (int u = 0; u < 16; u++)
            sp[(size_t)(t0 + u) * HID] = sv[u];
    }
    mem_final[idx] = mem;
}

// ---------------------------------------------------------------------------
// Launch
// ---------------------------------------------------------------------------
extern "C" void kernel_launch(void* const* d_in, const int* in_sizes, int n_in,
                              void* d_out, int out_size)
{
    const float* x = (const float*)d_in[0];   // [B, T, IN_DIM]
    const float* W = (const float*)d_in[1];   // [HID, IN_DIM]
    const float* b = (const float*)d_in[2];   // [HID]

    float* out        = (float*)d_out;
    float* spikes     = out;                                  // [B, T, H]
    float* mem_final  = out + (size_t)BATCH * TSTEPS * HID;   // [B, H]

    dim3 ggrid(HID / BN, MTOT / BM);    // (8, 256)
    snn_gemm_kernel<<<ggrid, 256>>>(x, W, b);

    snn_scan_kernel<<<(BATCH * HID) / 64, 64>>>(spikes, mem_final);
}